// round 17
// baseline (speedup 1.0000x reference)
#include <cuda_runtime.h>
#include <cstdint>

#define HD 128
#define WD 128
#define OC 128
#define CIN 64
#define HW (HD * WD)
#define XW 136                  // x word stride: 8q+w' distinct mod 32 (conflict-free frags)
#define XBUF (4 * 32 * XW)      // words per x buffer
#define WHALF 73728             // one o-half weight image (bytes)
#define NCTA 148
#define NPAIR 74
#define NTILE 1024

// smem byte offsets
#define SM_XB   0               // 2 * 69632 = 139264
#define SM_W    139264          // 73728
#define SM_CS   212992          // 2 * 2176 = 4352
#define SM_BIAS 217344          // 512
#define SM_MB   217856          // wb, full0, full1, free0, free1
#define SM_TOT  217904

// B fragments (bf16): [oh][tap][s(4)][g8(8)][lane(32)][2 words]
__device__ __align__(128) unsigned g_Wf[2 * 9 * 4 * 8 * 32 * 2];

// ---------- helpers ----------
__device__ __forceinline__ uint32_t smem_u32(const void* p) {
    uint32_t a;
    asm("{ .reg .u64 t; cvta.to.shared.u64 t, %1; cvt.u32.u64 %0, t; }" : "=r"(a) : "l"(p));
    return a;
}
__device__ __forceinline__ unsigned pack_bf2(float lo, float hi) {
    unsigned r;
    asm("cvt.rn.bf16x2.f32 %0, %1, %2;" : "=r"(r) : "f"(hi), "f"(lo));  // low = %2
    return r;
}
#define MB_INIT(mb, c)   asm volatile("mbarrier.init.shared.b64 [%0], %1;" :: "r"(mb), "r"((uint32_t)(c)) : "memory")
#define MB_EXPECT(mb, n) asm volatile("mbarrier.arrive.expect_tx.shared.b64 _, [%0], %1;" :: "r"(mb), "r"((uint32_t)(n)) : "memory")
#define MB_ARRIVE_REL(mb) asm volatile("mbarrier.arrive.release.cta.shared::cta.b64 _, [%0];" :: "r"(mb) : "memory")
#define BULK_G2S(dst, src, n, mb) \
    asm volatile("cp.async.bulk.shared::cta.global.mbarrier::complete_tx::bytes [%0], [%1], %2, [%3];" \
                 :: "r"(dst), "l"(src), "r"((uint32_t)(n)), "r"(mb) : "memory")
#define MB_WAIT(mb, par) do {                                                          \
    uint32_t _m = (mb), _p = (par), _d;                                                \
    asm volatile("{\n\t.reg .pred p;\n\t"                                              \
        "mbarrier.try_wait.parity.acquire.cta.shared::cta.b64 p, [%1], %2;\n\t"        \
        "selp.b32 %0,1,0,p;\n\t}" : "=r"(_d) : "r"(_m), "r"(_p) : "memory");           \
    if (!_d) {                                                                         \
        asm volatile("{\n\t.reg .pred P1;\n\tWL_%=:\n\t"                               \
            "mbarrier.try_wait.parity.acquire.cta.shared::cta.b64 P1, [%0], %1, 0x989680;\n\t" \
            "@P1 bra.uni WDN_%=;\n\tbra.uni WL_%=;\n\tWDN_%=:\n\t}"                    \
            :: "r"(_m), "r"(_p) : "memory");                                           \
    }                                                                                  \
} while (0)

// m16n8k16 bf16 HMMA (sm_80+ baseline ISA)
#define MMA16(d, av, bv)                                                               \
    asm volatile("mma.sync.aligned.m16n8k16.row.col.f32.bf16.bf16.f32 "                \
        "{%0,%1,%2,%3}, {%4,%5,%6,%7}, {%8,%9}, {%0,%1,%2,%3};"                        \
        : "+f"((d)[0]), "+f"((d)[1]), "+f"((d)[2]), "+f"((d)[3])                       \
        : "r"((av)[0]), "r"((av)[1]), "r"((av)[2]), "r"((av)[3]),                      \
          "r"((bv)[0]), "r"((bv)[1]))

// A frags for k-step ss from buffer base
#define LOAD_A(sl, base, rowci2, woff, ss) do {                                        \
    const unsigned* _p = (base) + ((rowci2) + (ss) * 8 + (lane & 3)) * XW + (woff);    \
    _Pragma("unroll") for (int _mi = 0; _mi < 4; _mi++) {                              \
        const unsigned* _q = _p + _mi * 16;                                            \
        a[sl][_mi][0] = _q[0];                                                         \
        a[sl][_mi][1] = _q[8];                                                         \
        a[sl][_mi][2] = _q[4 * XW];                                                    \
        a[sl][_mi][3] = _q[8 + 4 * XW];                                                \
    }                                                                                  \
} while (0)
// B frags (o-half image): per-tap tile 8192 B, [s][g8][lane][2]
#define LOAD_B2(sl, tap, ss) do {                                                      \
    const uint2* _bp = (const uint2*)(smem + SM_W + (tap) * 8192)                      \
                       + ((ss) * 8 + bgo) * 32 + lane;                                 \
    _Pragma("unroll") for (int _ni = 0; _ni < 4; _ni++) {                              \
        uint2 _v = _bp[_ni * 32];                                                      \
        b[sl][_ni][0] = _v.x; b[sl][_ni][1] = _v.y;                                    \
    }                                                                                  \
} while (0)

// ---------- prepass: weights -> bf16 frag images, o-half major ----------
__global__ void prep_w(const float* __restrict__ wt) {
    int i = blockIdx.x * blockDim.x + threadIdx.x;
    if (i >= 2 * 9 * 4 * 8 * 32 * 2) return;
    int oh  = i / 18432;
    int r   = i - oh * 18432;
    int tap = r / 2048;
    int r2  = r & 2047;
    int s    = r2 >> 9;
    int g8   = (r2 >> 6) & 7;
    int lane = (r2 >> 1) & 31;
    int jb   = r2 & 1;
    int o   = oh * 64 + g8 * 8 + (lane >> 2);
    int ci0 = s * 16 + jb * 8 + 2 * (lane & 3);
    float v0 = wt[o * 576 + ci0 * 9 + tap];
    float v1 = wt[o * 576 + (ci0 + 1) * 9 + tap];
    g_Wf[i] = pack_bf2(v0, v1);
}

// ---------- persistent kernel: 148 CTAs, 10 warps (8 consume + 2 produce) ----------
__global__ __launch_bounds__(320, 1)
void patchconv_mma(const float* __restrict__ x, const float* __restrict__ bias,
                   float* __restrict__ out) {
    extern __shared__ __align__(16) char smem[];
    unsigned* xw  = (unsigned*)(smem + SM_XB);
    float* scs    = (float*)(smem + SM_CS);
    float* sbias  = (float*)(smem + SM_BIAS);
    const uint32_t sb  = smem_u32(smem);
    const uint32_t wb0   = sb + SM_MB;
    const uint32_t full0 = sb + SM_MB + 8,  full1 = sb + SM_MB + 16;
    const uint32_t free0 = sb + SM_MB + 24, free1 = sb + SM_MB + 32;

    const int tid = threadIdx.x, lane = tid & 31, wid = tid >> 5;
    const int cta = blockIdx.x;
    const int cp  = cta >> 1;     // pair id 0..73
    const int oh  = cta & 1;      // o-half

    if (tid == 0) {
        MB_INIT(wb0, 1);
        MB_INIT(full0, 2); MB_INIT(full1, 2);
        MB_INIT(free0, 8); MB_INIT(free1, 8);
    }
    if (tid < 128) sbias[tid] = bias[tid];
    __syncthreads();
    if (tid == 0) {
        MB_EXPECT(wb0, WHALF);
        BULK_G2S(sb + SM_W, (const void*)(g_Wf + oh * 18432), WHALF, wb0);
    }

    if (wid >= 8) {
        // ================= producer warps (8,9): stage x tiles =================
        const int pw = wid - 8;
        int pr0 = 0, pr1 = 0;
        int j = 0;
        for (int t = cp; t < NTILE; t += NPAIR, j++) {
            const int s = j & 1;
            if (j >= 2) {
                if (s == 0) { MB_WAIT(free0, pr0); pr0 ^= 1; }
                else        { MB_WAIT(free1, pr1); pr1 ^= 1; }
            }
            const int h0 = (t & 63) * 2, bb = t >> 6;
            const float* xb = x + (size_t)bb * CIN * HW;
            unsigned* xdst = xw + s * XBUF;
            float* csd = scs + s * 544;
            for (int u = pw; u < 20; u += 2) {          // 4 rows x 5 w-chunks
                int r = u / 5, wc = u - r * 5;
                int w = wc * 32 + lane;                  // w = xcol + 1
                if (w < XW) {
                    int hr = h0 - 1 + r, xcol = w - 1;
                    bool ok = (w < 131) && ((unsigned)hr < 128u) && ((unsigned)xcol < 128u);
                    const float* sp = xb + (size_t)hr * WD + xcol;
                    float cs = 0.f;
                    unsigned* dst = xdst + (r * 32) * XW + w;
                    #pragma unroll 8
                    for (int c2 = 0; c2 < 32; c2++) {
                        float v0 = 0.f, v1 = 0.f;
                        if (ok) {
                            v0 = __ldg(sp + (size_t)(2 * c2) * HW);
                            v1 = __ldg(sp + (size_t)(2 * c2 + 1) * HW);
                        }
                        cs += v0 + v1;
                        dst[c2 * XW] = pack_bf2(v0, v1);
                    }
                    csd[r * XW + w] = cs;
                }
            }
            __syncwarp();
            if (lane == 0) MB_ARRIVE_REL(s ? full1 : full0);
        }
        return;
    }

    // ================= consumer warps (0-7): MMA + epilogue =================
    const int warp_m = wid >> 1, warp_n = wid & 1;
    const int hl  = warp_m >> 1;
    const int wbq = (warp_m & 1) * 64;
    const int bgo = warp_n * 4;                 // B g-group offset within o-half
    const int woffl = wbq + (lane >> 2);

    unsigned a[2][4][4];
    unsigned b[2][4][2];

    MB_WAIT(wb0, 0);                            // weights resident (once)

    int pf0 = 0, pf1 = 0;
    int k = 0;
    for (int t = cp; t < NTILE; t += NPAIR, k++) {
        const int s = k & 1;
        if (s == 0) { MB_WAIT(full0, pf0); pf0 ^= 1; }
        else        { MB_WAIT(full1, pf1); pf1 ^= 1; }

        const unsigned* xwb = xw + s * XBUF;
        const float* css = scs + s * 544;
        const int h0 = (t & 63) * 2, bb = t >> 6;

        float acc[4][4][4];
        #pragma unroll
        for (int mi = 0; mi < 4; mi++)
            #pragma unroll
            for (int ni = 0; ni < 4; ni++)
                #pragma unroll
                for (int j2 = 0; j2 < 4; j2++) acc[mi][ni][j2] = 0.f;

        LOAD_B2(0, 0, 0);
        LOAD_A(0, xwb, hl * 32, woffl, 0);

        #pragma unroll 1
        for (int kh = 0; kh < 3; kh++) {
            const int rowci2 = (hl + kh) * 32;
            #pragma unroll
            for (int s12 = 0; s12 < 12; s12++) {
                const int cur = s12 & 1, nxt = cur ^ 1;
                if (s12 < 11) {
                    const int ns = s12 + 1, nkw = ns >> 2, nss = ns & 3;
                    LOAD_B2(nxt, kh * 3 + nkw, nss);
                    LOAD_A(nxt, xwb, rowci2, woffl + nkw, nss);
                } else if (kh < 2) {
                    LOAD_B2(nxt, (kh + 1) * 3, 0);
                    LOAD_A(nxt, xwb, rowci2 + 32, woffl, 0);
                }
                #pragma unroll
                for (int mi = 0; mi < 4; mi++)
                    #pragma unroll
                    for (int ni = 0; ni < 4; ni++)
                        MMA16(acc[mi][ni], a[cur][mi], b[cur][ni]);
            }
        }

        // epilogue: inline 3x3 patch window + bias + rank-1, sector-aligned stores
        const int hg = h0 + hl;
        float* outb = out + (size_t)bb * OC * HW + (size_t)hg * WD;
        #pragma unroll
        for (int mi = 0; mi < 4; mi++) {
            int w0 = wbq + mi * 16 + (lane >> 2);
            float s0 = 0.f, s1 = 0.f;
            #pragma unroll
            for (int kh2 = 0; kh2 < 3; kh2++)
                #pragma unroll
                for (int kw2 = 0; kw2 < 3; kw2++) {
                    s0 += css[(hl + kh2) * XW + w0 + kw2];
                    s1 += css[(hl + kh2) * XW + w0 + 8 + kw2];
                }
            float c0 = 0.1f * (float)(hg + w0) * s0;
            float c1 = 0.1f * (float)(hg + w0 + 8) * s1;
            #pragma unroll
            for (int ni = 0; ni < 4; ni++) {
                int o = oh * 64 + warp_n * 32 + ni * 8 + 2 * (lane & 3);
                float bz0 = sbias[o], bz1 = sbias[o + 1];
                float* p0 = outb + (size_t)o * HW;
                float* p1 = p0 + HW;
                p0[w0]     = acc[mi][ni][0] + c0 + bz0;
                p1[w0]     = acc[mi][ni][1] + c0 + bz1;
                p0[w0 + 8] = acc[mi][ni][2] + c1 + bz0;
                p1[w0 + 8] = acc[mi][ni][3] + c1 + bz1;
            }
        }

        if (lane == 0) MB_ARRIVE_REL(s ? free1 : free0);
    }
}

extern "C" void kernel_launch(void* const* d_in, const int* in_sizes, int n_in,
                              void* d_out, int out_size) {
    const float* x    = (const float*)d_in[0];
    const float* wt   = (const float*)d_in[1];
    const float* bias = (const float*)d_in[2];
    float* out        = (float*)d_out;
    cudaFuncSetAttribute(patchconv_mma, cudaFuncAttributeMaxDynamicSharedMemorySize, SM_TOT);
    prep_w<<<(2 * 9 * 4 * 8 * 32 * 2 + 255) / 256, 256>>>(wt);
    patchconv_mma<<<NCTA, 320, SM_TOT>>>(x, bias, out);
}